// round 4
// baseline (speedup 1.0000x reference)
#include <cuda_runtime.h>

// Problem constants (fixed by the reference)
#define NH   8     // heads
#define FD   128   // per-step feature dim
#define DQKD 128   // q/k dim per head
#define DVD  16    // v dim per head
#define LL   50    // sequence length
#define LP   64    // padded sequence length

#define XTS  68    // xT row stride (floats): [FD][XTS], conflict-free float4 rows
#define YS   132   // Y row stride (floats):  [LP][YS], row-major
#define STS_ 68    // ST row stride (floats): [LP][STS_], S transposed [m][l]
#define VSS  16    // V row stride (floats):  [LP][VSS]

// Precomputed per-head folded weights (allocation-free scratch)
__device__ float g_A[NH][FD][FD];   // Wq @ Wk^T
__device__ float g_u[NH][FD];       // Wq @ bk
__device__ float g_w[NH][FD];       // Wk @ bq
__device__ float g_c[NH];           // bq . bk

// ---------------------------------------------------------------------------
// Kernel 1: fold Q/K weights
// ---------------------------------------------------------------------------
__global__ void precompute_kernel(const float* __restrict__ Wq,
                                  const float* __restrict__ bq,
                                  const float* __restrict__ Wk,
                                  const float* __restrict__ bk) {
    const int h     = blockIdx.x;
    const int slice = blockIdx.y;
    const int tid   = threadIdx.x;
    const float* wq = Wq + h * FD * DQKD;
    const float* wk = Wk + h * FD * DQKD;

    #pragma unroll
    for (int r = 0; r < 8; r++) {
        int o  = slice * 2048 + r * 256 + tid;
        int f  = o >> 7;
        int fp = o & 127;
        const float* qrow = wq + f * DQKD;
        const float* krow = wk + fp * DQKD;
        float acc = 0.f;
        #pragma unroll 8
        for (int e = 0; e < DQKD; e++) acc += qrow[e] * krow[e];
        g_A[h][f][fp] = acc;
    }
    if (slice == 0) {
        if (tid < FD) {
            float au = 0.f, aw = 0.f;
            #pragma unroll 8
            for (int e = 0; e < DQKD; e++) {
                au += wq[tid * DQKD + e] * bk[h * DQKD + e];
                aw += wk[tid * DQKD + e] * bq[h * DQKD + e];
            }
            g_u[h][tid] = au;
            g_w[h][tid] = aw;
        }
        if (tid == 128) {
            float c = 0.f;
            for (int e = 0; e < DQKD; e++) c += bq[h * DQKD + e] * bk[h * DQKD + e];
            g_c[h] = c;
        }
    }
}

// ---------------------------------------------------------------------------
// Kernel 2: fused attention, one CTA per batch row, float4 everywhere.
// ---------------------------------------------------------------------------
__global__ void __launch_bounds__(256, 2)
attn_main_kernel(const float* __restrict__ hid,
                 const float* __restrict__ Wv,
                 const float* __restrict__ bv,
                 float* __restrict__ out) {
    extern __shared__ float sm[];
    float* xT = sm;                      // [FD][XTS]   x transposed: xT[f][l]
    float* sY = xT + FD * XTS;           // [LP][YS]    Y row-major
    float* sT = sY + LP * YS;            // [LP][STS_]  S transposed: sT[m][l]
    float* sV = sT + LP * STS_;          // [LP][VSS]
    float* sp = sV + LP * VSS;           // [LP]
    float* sr = sp + LP;                 // [LP]

    const int tid = threadIdx.x;
    const int b   = blockIdx.x;
    const float* xg = hid + (long long)b * (LL * FD);

    // load + transpose x into xT[f][l], zero-pad l in [50,64)
    for (int i = tid; i < LP * FD; i += 256) {
        int l = i >> 7, f = i & 127;
        xT[f * XTS + l] = (l < LL) ? xg[l * FD + f] : 0.f;
    }
    __syncthreads();

    const int te  = (tid & 15) * 8;   // e-base (stage a)
    const int tl  = (tid >> 4) * 4;   // l-base (stages a, c)
    const int jm  = (tid & 15) * 4;   // m-base (stage c)
    const int fl  = tid >> 2;         // l for stages e/f (0..63)
    const int dvb = (tid & 3) * 4;    // dv base for stages e/f

    for (int h = 0; h < NH; h++) {
        // ---- (a) Y = x @ A_h : 64x128, thread tile 4l x 8e, f-reduction ----
        {
            const float* Ah = &g_A[h][0][0];
            float acc[4][8];
            #pragma unroll
            for (int a = 0; a < 4; a++)
                #pragma unroll
                for (int e = 0; e < 8; e++) acc[a][e] = 0.f;

            #pragma unroll 4
            for (int f = 0; f < FD; f++) {
                float4 xv = *(const float4*)(xT + f * XTS + tl);
                float4 a0 = *(const float4*)(Ah + f * FD + te);
                float4 a1 = *(const float4*)(Ah + f * FD + te + 4);
                const float xa[4] = {xv.x, xv.y, xv.z, xv.w};
                #pragma unroll
                for (int a = 0; a < 4; a++) {
                    acc[a][0] += xa[a] * a0.x;  acc[a][1] += xa[a] * a0.y;
                    acc[a][2] += xa[a] * a0.z;  acc[a][3] += xa[a] * a0.w;
                    acc[a][4] += xa[a] * a1.x;  acc[a][5] += xa[a] * a1.y;
                    acc[a][6] += xa[a] * a1.z;  acc[a][7] += xa[a] * a1.w;
                }
            }
            #pragma unroll
            for (int a = 0; a < 4; a++) {
                float4 s0 = make_float4(acc[a][0], acc[a][1], acc[a][2], acc[a][3]);
                float4 s1 = make_float4(acc[a][4], acc[a][5], acc[a][6], acc[a][7]);
                *(float4*)(sY + (tl + a) * YS + te)     = s0;
                *(float4*)(sY + (tl + a) * YS + te + 4) = s1;
            }
        }
        // ---- (b) p[l] = x_l.u + c ;  r[m] = x_m.w ----
        if (tid < LP) {
            const int l = tid;
            float acc = g_c[h];
            #pragma unroll 8
            for (int f = 0; f < FD; f++) acc += xT[f * XTS + l] * g_u[h][f];
            sp[l] = acc;
        } else if (tid < 2 * LP) {
            const int m = tid - LP;
            float acc = 0.f;
            #pragma unroll 8
            for (int f = 0; f < FD; f++) acc += xT[f * XTS + m] * g_w[h][f];
            sr[m] = acc;
        }
        __syncthreads();

        // ---- (c) S = Y x^T + p + r, leaky; store transposed sT[m][l] ----
        {
            float acc[4][4];
            #pragma unroll
            for (int a = 0; a < 4; a++)
                #pragma unroll
                for (int c2 = 0; c2 < 4; c2++) acc[a][c2] = 0.f;

            #pragma unroll 2
            for (int e = 0; e < FD; e += 4) {
                float4 yv[4], xv[4];
                #pragma unroll
                for (int a = 0; a < 4; a++)
                    yv[a] = *(const float4*)(sY + (tl + a) * YS + e);
                #pragma unroll
                for (int q = 0; q < 4; q++)
                    xv[q] = *(const float4*)(xT + (e + q) * XTS + jm);
                #pragma unroll
                for (int a = 0; a < 4; a++) {
                    acc[a][0] += yv[a].x * xv[0].x + yv[a].y * xv[1].x
                               + yv[a].z * xv[2].x + yv[a].w * xv[3].x;
                    acc[a][1] += yv[a].x * xv[0].y + yv[a].y * xv[1].y
                               + yv[a].z * xv[2].y + yv[a].w * xv[3].y;
                    acc[a][2] += yv[a].x * xv[0].z + yv[a].y * xv[1].z
                               + yv[a].z * xv[2].z + yv[a].w * xv[3].z;
                    acc[a][3] += yv[a].x * xv[0].w + yv[a].y * xv[1].w
                               + yv[a].z * xv[2].w + yv[a].w * xv[3].w;
                }
            }
            float pl[4];
            #pragma unroll
            for (int a = 0; a < 4; a++) pl[a] = sp[tl + a];
            #pragma unroll
            for (int c2 = 0; c2 < 4; c2++) {
                float rm = sr[jm + c2];
                float4 w;
                float v0 = acc[0][c2] + pl[0] + rm;
                float v1 = acc[1][c2] + pl[1] + rm;
                float v2 = acc[2][c2] + pl[2] + rm;
                float v3 = acc[3][c2] + pl[3] + rm;
                w.x = v0 > 0.f ? v0 : 0.1f * v0;
                w.y = v1 > 0.f ? v1 : 0.1f * v1;
                w.z = v2 > 0.f ? v2 : 0.1f * v2;
                w.w = v3 > 0.f ? v3 : 0.1f * v3;
                *(float4*)(sT + (jm + c2) * STS_ + tl) = w;
            }
        }
        __syncthreads();

        // ---- (d) softmax over l (rows of sT), thread m owns row m ----
        if (tid < LL) {
            float* row = sT + tid * STS_;
            float mx = -1e30f;
            #pragma unroll 10
            for (int l = 0; l < LL; l++) mx = fmaxf(mx, row[l]);
            float sum = 0.f;
            #pragma unroll 10
            for (int l = 0; l < LL; l++) {
                float e = __expf(row[l] - mx);
                row[l] = e;
                sum += e;
            }
            float inv = 1.f / sum;
            #pragma unroll 10
            for (int l = 0; l < LL; l++) row[l] *= inv;
        }
        // ---- (e) V = x @ Wv_h + bv (independent of softmax) ----
        {
            const float* wvh = Wv + h * FD * DVD;
            float4 acc = *(const float4*)(bv + h * DVD + dvb);
            #pragma unroll 4
            for (int f = 0; f < FD; f++) {
                float xs = xT[f * XTS + fl];
                float4 wv = *(const float4*)(wvh + f * DVD + dvb);
                acc.x += xs * wv.x;  acc.y += xs * wv.y;
                acc.z += xs * wv.z;  acc.w += xs * wv.w;
            }
            *(float4*)(sV + fl * VSS + dvb) = acc;
        }
        __syncthreads();

        // ---- (f) out = relu(att @ V), att[l][m] = sT[m][l] ----
        if (fl < LL) {
            float4 acc = make_float4(0.f, 0.f, 0.f, 0.f);
            #pragma unroll 10
            for (int m = 0; m < LL; m++) {
                float s = sT[m * STS_ + fl];
                float4 vv = *(const float4*)(sV + m * VSS + dvb);
                acc.x += s * vv.x;  acc.y += s * vv.y;
                acc.z += s * vv.z;  acc.w += s * vv.w;
            }
            acc.x = fmaxf(acc.x, 0.f);  acc.y = fmaxf(acc.y, 0.f);
            acc.z = fmaxf(acc.z, 0.f);  acc.w = fmaxf(acc.w, 0.f);
            *(float4*)(out + (long long)b * (LL * NH * DVD)
                           + fl * (NH * DVD) + h * DVD + dvb) = acc;
        }
        __syncthreads();
    }
}

// ---------------------------------------------------------------------------
extern "C" void kernel_launch(void* const* d_in, const int* in_sizes, int n_in,
                              void* d_out, int out_size) {
    const float* hid = (const float*)d_in[0];
    const float* Wq  = (const float*)d_in[1];
    const float* bq  = (const float*)d_in[2];
    const float* Wk  = (const float*)d_in[3];
    const float* bk  = (const float*)d_in[4];
    const float* Wv  = (const float*)d_in[5];
    const float* bv  = (const float*)d_in[6];
    float* out = (float*)d_out;

    const int nb = in_sizes[0] / (LL * FD);

    const int smem_bytes =
        (FD * XTS + LP * YS + LP * STS_ + LP * VSS + 2 * LP) * sizeof(float);
    cudaFuncSetAttribute(attn_main_kernel,
                         cudaFuncAttributeMaxDynamicSharedMemorySize, smem_bytes);

    precompute_kernel<<<dim3(NH, 8), 256>>>(Wq, bq, Wk, bk);
    attn_main_kernel<<<nb, 256, smem_bytes>>>(hid, Wv, bv, out);
}

// round 6
// speedup vs baseline: 2.6197x; 2.6197x over previous
#include <cuda_runtime.h>
#include <cuda_bf16.h>
#include <cstdint>

#define NH   8
#define FD   128
#define DVD  16
#define LL   50

// ---------------- smem layout (bytes) ----------------
#define OFF_SP   0                      // p[2][64] f32
#define OFF_SR   512                    // r[2][64] f32
#define OFF_XHI  1024                   // X hi [128][256B] swizzled bf16
#define OFF_XLO  (OFF_XHI + 32768)
#define OFF_BHI  (OFF_XLO + 32768)      // At hi, then Y hi
#define OFF_BLO  (OFF_BHI + 32768)      // At lo, then Y lo
#define OFF_WHI  (OFF_BLO + 32768)      // Wvt hi [16][256B]
#define OFF_WLO  (OFF_WHI + 4096)
#define OFF_V    (OFF_WLO + 4096)       // V f32 [2][64][16]
#define OFF_P    (OFF_V + 8192)         // P f32 [2][64][65]
#define SMEM_TOTAL (OFF_P + 2*64*65*4)  // 181760

// ------------- precomputed folded weights -------------
__device__ __align__(16) __nv_bfloat16 g_Ahi[NH][128 * 128];
__device__ __align__(16) __nv_bfloat16 g_Alo[NH][128 * 128];
__device__ __align__(16) __nv_bfloat16 g_Whi[NH][16 * 128];
__device__ __align__(16) __nv_bfloat16 g_Wlo[NH][16 * 128];
__device__ float g_u[NH][FD];
__device__ float g_w[NH][FD];
__device__ float g_c[NH];

// swizzled byte offset in a [rows][128 bf16] tile (256B rows, 16B-chunk XOR)
__host__ __device__ __forceinline__ uint32_t xoff(int r, int c) {
    return (uint32_t)r * 256u
         + (uint32_t)(((((c >> 3) ^ (r & 7))) << 4) + (c & 7) * 2);
}

// ---------------- PTX helpers ----------------
__device__ __forceinline__ uint32_t smem_u32(const void* p) {
    uint32_t a;
    asm("{ .reg .u64 t; cvta.to.shared.u64 t, %1; cvt.u32.u64 %0, t; }"
        : "=r"(a) : "l"(p));
    return a;
}
__device__ __forceinline__ void ldsm_x4(uint32_t a[4], uint32_t addr) {
    asm volatile("ldmatrix.sync.aligned.m8n8.x4.shared.b16 {%0,%1,%2,%3}, [%4];"
                 : "=r"(a[0]), "=r"(a[1]), "=r"(a[2]), "=r"(a[3]) : "r"(addr));
}
__device__ __forceinline__ void ldsm_x2(uint32_t a[2], uint32_t addr) {
    asm volatile("ldmatrix.sync.aligned.m8n8.x2.shared.b16 {%0,%1}, [%2];"
                 : "=r"(a[0]), "=r"(a[1]) : "r"(addr));
}
__device__ __forceinline__ void mma16816(float c[4], const uint32_t a[4],
                                         const uint32_t b[2]) {
    asm volatile(
        "mma.sync.aligned.m16n8k16.row.col.f32.bf16.bf16.f32 "
        "{%0,%1,%2,%3}, {%4,%5,%6,%7}, {%8,%9}, {%0,%1,%2,%3};"
        : "+f"(c[0]), "+f"(c[1]), "+f"(c[2]), "+f"(c[3])
        : "r"(a[0]), "r"(a[1]), "r"(a[2]), "r"(a[3]), "r"(b[0]), "r"(b[1]));
}
#define CP_ASYNC16(s, g) \
    asm volatile("cp.async.cg.shared.global [%0], [%1], 16;" :: "r"(s), "l"(g))
#define CP_COMMIT() asm volatile("cp.async.commit_group;" ::: "memory")
#define CP_WAIT0()  asm volatile("cp.async.wait_group 0;" ::: "memory")

__device__ __forceinline__ uint32_t pack_bf16(float v0, float v1) {
    __nv_bfloat162 t = __floats2bfloat162_rn(v0, v1);
    return *(uint32_t*)&t;
}

// ---------------------------------------------------------------------------
// Kernel 1: fold A = Wq Wk^T (bf16 hi/lo, swizzled At), Wvt hi/lo, biases
// ---------------------------------------------------------------------------
__global__ void precompute_kernel(const float* __restrict__ Wq,
                                  const float* __restrict__ bq,
                                  const float* __restrict__ Wk,
                                  const float* __restrict__ bk,
                                  const float* __restrict__ Wv) {
    const int h     = blockIdx.x;
    const int slice = blockIdx.y;
    const int tid   = threadIdx.x;
    const float* wq = Wq + h * FD * 128;
    const float* wk = Wk + h * FD * 128;

    #pragma unroll
    for (int r = 0; r < 8; r++) {
        int o  = slice * 2048 + r * 256 + tid;
        int f  = o >> 7;
        int fp = o & 127;
        const float* qrow = wq + f * 128;
        const float* krow = wk + fp * 128;
        float acc = 0.f;
        #pragma unroll 8
        for (int e = 0; e < 128; e++) acc += qrow[e] * krow[e];
        // At[fp][f] = A[f][fp]
        __nv_bfloat16 hi = __float2bfloat16(acc);
        float rem = acc - __bfloat162float(hi);
        uint32_t off = xoff(fp, f);
        *(__nv_bfloat16*)((char*)g_Ahi[h] + off) = hi;
        *(__nv_bfloat16*)((char*)g_Alo[h] + off) = __float2bfloat16(rem);
    }
    if (slice == 0) {
        // Wvt[dv][f] = Wv[h][f][dv], split hi/lo
        #pragma unroll
        for (int it = 0; it < 8; it++) {
            int idx = it * 256 + tid;        // 0..2047
            int dv = idx >> 7, f = idx & 127;
            float v = Wv[h * FD * DVD + f * DVD + dv];
            __nv_bfloat16 hi = __float2bfloat16(v);
            float rem = v - __bfloat162float(hi);
            uint32_t off = xoff(dv, f);
            *(__nv_bfloat16*)((char*)g_Whi[h] + off) = hi;
            *(__nv_bfloat16*)((char*)g_Wlo[h] + off) = __float2bfloat16(rem);
        }
        if (tid < FD) {
            float au = 0.f, aw = 0.f;
            #pragma unroll 8
            for (int e = 0; e < 128; e++) {
                au += wq[tid * 128 + e] * bk[h * 128 + e];
                aw += wk[tid * 128 + e] * bq[h * 128 + e];
            }
            g_u[h][tid] = au;
            g_w[h][tid] = aw;
        }
        if (tid == 128) {
            float c = 0.f;
            for (int e = 0; e < 128; e++) c += bq[h * 128 + e] * bk[h * 128 + e];
            g_c[h] = c;
        }
    }
}

// ---------------------------------------------------------------------------
// Kernel 2: HMMA attention, 2 batches per CTA (M = 128 stacked rows).
// ---------------------------------------------------------------------------
__global__ void __launch_bounds__(256, 1)
attn_mma_kernel(const float* __restrict__ hid,
                const float* __restrict__ bv,
                float* __restrict__ out) {
    extern __shared__ char smc[];
    const uint32_t sb = smem_u32(smc);
    const int tid  = threadIdx.x;
    const int wid  = tid >> 5;
    const int lane = tid & 31;
    const int bid  = blockIdx.x;

    float* spf = (float*)(smc + OFF_SP);
    float* srf = (float*)(smc + OFF_SR);
    float* sVf = (float*)(smc + OFF_V);
    float* sPf = (float*)(smc + OFF_P);

    // ---- load x (2 batches), bf16 hi/lo split, swizzled ----
    for (int i = tid; i < 128 * 64; i += 256) {
        int row = i >> 6;
        int cp  = (i & 63) * 2;
        int bb = row >> 6, l = row & 63;
        float v0 = 0.f, v1 = 0.f;
        if (l < LL) {
            const float* xr = hid + (long long)(2 * bid + bb) * (LL * FD) + l * FD + cp;
            v0 = xr[0]; v1 = xr[1];
        }
        __nv_bfloat16 h0 = __float2bfloat16(v0), h1 = __float2bfloat16(v1);
        float r0 = v0 - __bfloat162float(h0), r1 = v1 - __bfloat162float(h1);
        uint32_t off = xoff(row, cp);
        *(uint32_t*)(smc + OFF_XHI + off) =
            ((uint32_t)__bfloat16_as_ushort(h1) << 16) | __bfloat16_as_ushort(h0);
        *(uint32_t*)(smc + OFF_XLO + off) = pack_bf16(r0, r1);
    }
    __syncthreads();

    // ---- ldmatrix lane-address components ----
    const int lr   = lane & 7;
    const int quad = lane >> 3;                 // A x4 quadrant
    const uint32_t rA = (uint32_t)((wid << 4) + lr + ((quad & 1) << 3));
    const int ahalf = quad >> 1;                // A k-half
    const int i15  = lane & 15;                 // B x2 lanes
    const int blr  = i15 & 7;
    const int bhalf = i15 >> 3;
    const uint32_t aRowOff = rA * 256u;
    const uint32_t bRowOff = (uint32_t)blr * 256u;
    const int g  = lane >> 2;                   // C fragment row in group
    const int tg = lane & 3;                    // C fragment col pair

    for (int h = 0; h < NH; h++) {
        // ======== stage A: stage At/Wvt via cp.async; p/r scalar ========
        {
            const char* gh = (const char*)g_Ahi[h];
            const char* gl = (const char*)g_Alo[h];
            #pragma unroll
            for (int j = 0; j < 8; j++) {
                uint32_t o = (uint32_t)(j * 4096 + tid * 16);
                CP_ASYNC16(sb + OFF_BHI + o, gh + o);
                CP_ASYNC16(sb + OFF_BLO + o, gl + o);
            }
            CP_ASYNC16(sb + OFF_WHI + tid * 16, (const char*)g_Whi[h] + tid * 16);
            CP_ASYNC16(sb + OFF_WLO + tid * 16, (const char*)g_Wlo[h] + tid * 16);
            CP_COMMIT();
        }
        {   // p[l] = x_l.u + c ; r[m] = x_m.w  (overlaps the copy)
            int bb = tid >> 7, which = (tid >> 6) & 1, idx = tid & 63;
            float acc = which ? 0.f : g_c[h];
            if (idx < LL) {
                const float* xr = hid + (long long)(2 * bid + bb) * (LL * FD) + idx * FD;
                const float* vec = which ? g_w[h] : g_u[h];
                #pragma unroll 4
                for (int f = 0; f < FD; f += 4) {
                    float4 xq = *(const float4*)(xr + f);
                    acc += xq.x * vec[f] + xq.y * vec[f + 1]
                         + xq.z * vec[f + 2] + xq.w * vec[f + 3];
                }
            }
            (which ? srf : spf)[bb * 64 + idx] = acc;
        }
        CP_WAIT0();
        __syncthreads();

        // ======== stage B: GEMM1  Y = X·Atᵀ (16 tiles) + V = X·Wvtᵀ (2) ====
        float cY[16][4];
        float cV[2][4];
        #pragma unroll
        for (int n = 0; n < 16; n++)
            #pragma unroll
            for (int q = 0; q < 4; q++) cY[n][q] = 0.f;
        #pragma unroll
        for (int n = 0; n < 2; n++)
            #pragma unroll
            for (int q = 0; q < 4; q++) cV[n][q] = 0.f;

        #pragma unroll
        for (int k = 0; k < 8; k++) {
            uint32_t ca = (uint32_t)(((2 * k + ahalf) ^ lr) << 4);
            uint32_t ahi[4], alo[4];
            ldsm_x4(ahi, sb + OFF_XHI + aRowOff + ca);
            ldsm_x4(alo, sb + OFF_XLO + aRowOff + ca);
            uint32_t cb = (uint32_t)(((2 * k + bhalf) ^ blr) << 4);
            uint32_t bo = bRowOff + cb;
            #pragma unroll
            for (int n = 0; n < 16; n++) {
                uint32_t o = bo + (uint32_t)(n * 2048);
                uint32_t bh[2], bl[2];
                ldsm_x2(bh, sb + OFF_BHI + o);
                ldsm_x2(bl, sb + OFF_BLO + o);
                mma16816(cY[n], ahi, bh);
                mma16816(cY[n], ahi, bl);
                mma16816(cY[n], alo, bh);
            }
            #pragma unroll
            for (int n = 0; n < 2; n++) {
                uint32_t o = bo + (uint32_t)(n * 2048);
                uint32_t bh[2], bl[2];
                ldsm_x2(bh, sb + OFF_WHI + o);
                ldsm_x2(bl, sb + OFF_WLO + o);
                mma16816(cV[n], ahi, bh);
                mma16816(cV[n], ahi, bl);
                mma16816(cV[n], alo, bh);
            }
        }
        __syncthreads();   // all warps done reading At before overwrite

        // ======== stage C: store Y (hi/lo into B buffers) and V ========
        {
            const int row0 = wid << 4;
            #pragma unroll
            for (int n = 0; n < 16; n++) {
                int col = n * 8 + tg * 2;
                uint32_t o0 = xoff(row0 + g, col);
                uint32_t o1 = xoff(row0 + 8 + g, col);
                float y0 = cY[n][0], y1 = cY[n][1];
                float y2 = cY[n][2], y3 = cY[n][3];
                __nv_bfloat16 h0 = __float2bfloat16(y0), h1 = __float2bfloat16(y1);
                __nv_bfloat16 h2 = __float2bfloat16(y2), h3 = __float2bfloat16(y3);
                *(uint32_t*)(smc + OFF_BHI + o0) =
                    ((uint32_t)__bfloat16_as_ushort(h1) << 16) | __bfloat16_as_ushort(h0);
                *(uint32_t*)(smc + OFF_BHI + o1) =
                    ((uint32_t)__bfloat16_as_ushort(h3) << 16) | __bfloat16_as_ushort(h2);
                *(uint32_t*)(smc + OFF_BLO + o0) =
                    pack_bf16(y0 - __bfloat162float(h0), y1 - __bfloat162float(h1));
                *(uint32_t*)(smc + OFF_BLO + o1) =
                    pack_bf16(y2 - __bfloat162float(h2), y3 - __bfloat162float(h3));
            }
            const int bb = row0 >> 6, ml = (row0 & 63) + g;
            #pragma unroll
            for (int n = 0; n < 2; n++) {
                int dv = n * 8 + tg * 2;
                float b0 = bv[h * DVD + dv], b1 = bv[h * DVD + dv + 1];
                float* v0 = sVf + (bb * 64 + ml) * 16 + dv;
                float* v1 = sVf + (bb * 64 + ml + 8) * 16 + dv;
                v0[0] = cV[n][0] + b0;  v0[1] = cV[n][1] + b1;
                v1[0] = cV[n][2] + b0;  v1[1] = cV[n][3] + b1;
            }
        }
        __syncthreads();

        // ======== stage D: GEMM2  C2[m,l] = X·Yᵀ (per batch) ========
        float cS[8][4];
        #pragma unroll
        for (int n = 0; n < 8; n++)
            #pragma unroll
            for (int q = 0; q < 4; q++) cS[n][q] = 0.f;
        const int bb = wid >> 2;
        const uint32_t ybase = (uint32_t)(bb * 64 * 256);
        #pragma unroll
        for (int k = 0; k < 8; k++) {
            uint32_t ca = (uint32_t)(((2 * k + ahalf) ^ lr) << 4);
            uint32_t ahi[4], alo[4];
            ldsm_x4(ahi, sb + OFF_XHI + aRowOff + ca);
            ldsm_x4(alo, sb + OFF_XLO + aRowOff + ca);
            uint32_t cb = (uint32_t)(((2 * k + bhalf) ^ blr) << 4);
            uint32_t bo = ybase + bRowOff + cb;
            #pragma unroll
            for (int n = 0; n < 8; n++) {
                uint32_t o = bo + (uint32_t)(n * 2048);
                uint32_t bh[2], bl[2];
                ldsm_x2(bh, sb + OFF_BHI + o);
                ldsm_x2(bl, sb + OFF_BLO + o);
                mma16816(cS[n], ahi, bh);
                mma16816(cS[n], ahi, bl);
                mma16816(cS[n], alo, bh);
            }
        }

        // ======== stage E: bias + leaky + softmax over l, P -> smem ========
        {
            const int mbase = ((wid & 3) << 4) + g;
            #pragma unroll
            for (int pair = 0; pair < 2; pair++) {
                const int m = mbase + pair * 8;
                const float rm = srf[bb * 64 + m];
                float vals[16];
                float mx = -1e30f;
                #pragma unroll
                for (int n = 0; n < 8; n++) {
                    #pragma unroll
                    for (int j = 0; j < 2; j++) {
                        int l = n * 8 + tg * 2 + j;
                        float v = cS[n][pair * 2 + j] + spf[bb * 64 + l] + rm;
                        v = v > 0.f ? v : 0.1f * v;
                        if (l >= LL) v = -1e30f;
                        vals[n * 2 + j] = v;
                        mx = fmaxf(mx, v);
                    }
                }
                mx = fmaxf(mx, __shfl_xor_sync(0xffffffffu, mx, 1));
                mx = fmaxf(mx, __shfl_xor_sync(0xffffffffu, mx, 2));
                float sum = 0.f;
                #pragma unroll
                for (int q = 0; q < 16; q++) {
                    float e = __expf(vals[q] - mx);
                    vals[q] = e;
                    sum += e;
                }
                sum += __shfl_xor_sync(0xffffffffu, sum, 1);
                sum += __shfl_xor_sync(0xffffffffu, sum, 2);
                float inv = 1.f / sum;
                float* prow = sPf + (bb * 64 + m) * 65;
                #pragma unroll
                for (int n = 0; n < 8; n++) {
                    prow[n * 8 + tg * 2]     = vals[n * 2] * inv;
                    prow[n * 8 + tg * 2 + 1] = vals[n * 2 + 1] * inv;
                }
            }
        }
        __syncthreads();

        // ======== stage F: out = relu(Pᵀ·V), store head slice ========
        #pragma unroll
        for (int it = 0; it < 2; it++) {
            int item = tid + it * 256;
            int b2 = item >> 8, l = (item >> 2) & 63, dv = (item & 3) * 4;
            if (l < LL) {
                float4 acc = make_float4(0.f, 0.f, 0.f, 0.f);
                const float* pcol = sPf + b2 * 64 * 65 + l;
                const float* vb   = sVf + b2 * 1024 + dv;
                #pragma unroll 10
                for (int m = 0; m < LL; m++) {
                    float p = pcol[m * 65];
                    float4 vv = *(const float4*)(vb + m * 16);
                    acc.x += p * vv.x;  acc.y += p * vv.y;
                    acc.z += p * vv.z;  acc.w += p * vv.w;
                }
                acc.x = fmaxf(acc.x, 0.f);  acc.y = fmaxf(acc.y, 0.f);
                acc.z = fmaxf(acc.z, 0.f);  acc.w = fmaxf(acc.w, 0.f);
                *(float4*)(out + (long long)(2 * bid + b2) * (LL * NH * DVD)
                               + l * (NH * DVD) + h * DVD + dv) = acc;
            }
        }
        __syncthreads();
    }
}

// ---------------------------------------------------------------------------
extern "C" void kernel_launch(void* const* d_in, const int* in_sizes, int n_in,
                              void* d_out, int out_size) {
    const float* hid = (const float*)d_in[0];
    const float* Wq  = (const float*)d_in[1];
    const float* bq  = (const float*)d_in[2];
    const float* Wk  = (const float*)d_in[3];
    const float* bk  = (const float*)d_in[4];
    const float* Wv  = (const float*)d_in[5];
    const float* bv  = (const float*)d_in[6];
    float* out = (float*)d_out;

    const int nb = in_sizes[0] / (LL * FD);

    cudaFuncSetAttribute(attn_mma_kernel,
                         cudaFuncAttributeMaxDynamicSharedMemorySize, SMEM_TOTAL);

    precompute_kernel<<<dim3(NH, 8), 256>>>(Wq, bq, Wk, bk, Wv);
    attn_mma_kernel<<<nb / 2, 256, SMEM_TOTAL>>>(hid, bv, out);
}